// round 7
// baseline (speedup 1.0000x reference)
#include <cuda_runtime.h>
#include <cstdint>

// Problem constants
#define BTOK  65536
#define HID   512
#define DIN   512
#define NEXP  64
#define FOURE 256

// ---------------- scratch (static __device__, no allocation) ----------------
__device__ float g_q1[(size_t)BTOK * HID];   // qe1 output, reused for fused
__device__ float g_q [(size_t)BTOK * HID];   // qe2 output
__device__ float g_t [(size_t)BTOK * FOURE]; // tanh(fused @ Wg1^T)
__device__ float g_l [(size_t)BTOK * NEXP];  // logits

// ---------------- packed f32x2 helpers (sm_103a) ----------------------------
typedef unsigned long long u64;

__device__ __forceinline__ u64 fma2(u64 a, u64 b, u64 c) {
    u64 d;
    asm("fma.rn.f32x2 %0, %1, %2, %3;" : "=l"(d) : "l"(a), "l"(b), "l"(c));
    return d;
}
__device__ __forceinline__ u64 add2(u64 a, u64 b) {
    u64 d;
    asm("add.rn.f32x2 %0, %1, %2;" : "=l"(d) : "l"(a), "l"(b));
    return d;
}
__device__ __forceinline__ u64 dup2(float x) {
    u64 d;
    asm("mov.b64 %0, {%1, %1};" : "=l"(d) : "f"(x));
    return d;
}
__device__ __forceinline__ float2 unpk2(u64 a) {
    float2 r;
    asm("mov.b64 {%0, %1}, %2;" : "=f"(r.x), "=f"(r.y) : "l"(a));
    return r;
}

// ---------------- chunked-Kahan tiled fp32 GEMM: C = act(A @ W^T) -----------
// Each BKK=16 k-tile accumulates with plain packed FMA into P (1 op / 2 MACs);
// P is folded into (S, Cn) with a packed Kahan step (Cn = -compensation).
// LDS budget per k-step: 2x LDS.128 (a-quad, broadcast) + 2x LDS.128
// (pre-duplicated b-pairs) = 4 LDS instr for 16 fma2 -> FMA-pipe bound.
// A is logically [M, K]; columns [0,K0) from A0 (row stride K0), columns
// [K0,K) from A1 (row stride K-K0).  W is [N, K] row-major.
#define BM 128
#define BN 64
#define BKK 16

__global__ __launch_bounds__(256, 2) void gemm_bias_act(
    const float* __restrict__ A0, const float* __restrict__ A1, int K0, int K,
    const float* __restrict__ W, const float* __restrict__ bias,
    float* __restrict__ C, int N, int act)
{
    __shared__ __align__(16) float As[BKK][BM];
    __shared__ __align__(16) u64   Bsd[BKK][BN];   // (b, b) duplicated pairs

    const int tid  = threadIdx.x;
    const int m0   = blockIdx.y * BM;
    const int n0   = blockIdx.x * BN;
    const int lr   = tid >> 2;          // 0..63
    const int lc   = (tid & 3) << 2;    // 0,4,8,12 (float4 col)
    const int trow = (tid >> 4) << 3;   // 0..120 step 8
    const int tcol = (tid & 15) << 2;   // 0..60 step 4

    const u64 MONE = 0xbf800000bf800000ULL;  // (-1.0f, -1.0f)

    // S[pi][j]: rows (trow+2pi, trow+2pi+1), col tcol+j.  Cn = -compensation.
    u64 S[4][4], Cn[4][4];
#pragma unroll
    for (int pi = 0; pi < 4; pi++)
#pragma unroll
        for (int j = 0; j < 4; j++) { S[pi][j] = 0ull; Cn[pi][j] = 0ull; }

    for (int kt = 0; kt < K; kt += BKK) {
        const int gk = kt + lc;
        float4 av0, av1;
        if (gk < K0) {
            av0 = *(const float4*)(A0 + (size_t)(m0 + lr)      * K0 + gk);
            av1 = *(const float4*)(A0 + (size_t)(m0 + lr + 64) * K0 + gk);
        } else {
            const int K1 = K - K0;
            av0 = *(const float4*)(A1 + (size_t)(m0 + lr)      * K1 + (gk - K0));
            av1 = *(const float4*)(A1 + (size_t)(m0 + lr + 64) * K1 + (gk - K0));
        }
        const float4 bv = *(const float4*)(W + (size_t)(n0 + lr) * K + gk);

        As[lc + 0][lr] = av0.x; As[lc + 1][lr] = av0.y;
        As[lc + 2][lr] = av0.z; As[lc + 3][lr] = av0.w;
        As[lc + 0][lr + 64] = av1.x; As[lc + 1][lr + 64] = av1.y;
        As[lc + 2][lr + 64] = av1.z; As[lc + 3][lr + 64] = av1.w;

        Bsd[lc + 0][lr] = dup2(bv.x); Bsd[lc + 1][lr] = dup2(bv.y);
        Bsd[lc + 2][lr] = dup2(bv.z); Bsd[lc + 3][lr] = dup2(bv.w);

        __syncthreads();

        // chunk accumulators (plain packed FMA, 16 independent chains)
        u64 P[4][4];
#pragma unroll
        for (int pi = 0; pi < 4; pi++)
#pragma unroll
            for (int j = 0; j < 4; j++) P[pi][j] = 0ull;

#pragma unroll
        for (int k = 0; k < BKK; k++) {
            const ulonglong2 aq0 = *(const ulonglong2*)&As[k][trow];      // LDS.128
            const ulonglong2 aq1 = *(const ulonglong2*)&As[k][trow + 4];  // LDS.128
            u64 ap[4] = { aq0.x, aq0.y, aq1.x, aq1.y };
            const ulonglong2 bq0 = *(const ulonglong2*)&Bsd[k][tcol];     // LDS.128
            const ulonglong2 bq1 = *(const ulonglong2*)&Bsd[k][tcol + 2]; // LDS.128
            u64 bd[4] = { bq0.x, bq0.y, bq1.x, bq1.y };
#pragma unroll
            for (int j = 0; j < 4; j++)
#pragma unroll
                for (int pi = 0; pi < 4; pi++)
                    P[pi][j] = fma2(ap[pi], bd[j], P[pi][j]);
        }

        // Kahan fold of chunk sums into (S, Cn)
#pragma unroll
        for (int pi = 0; pi < 4; pi++)
#pragma unroll
            for (int j = 0; j < 4; j++) {
                u64 y = add2(P[pi][j], Cn[pi][j]);
                u64 t = add2(S[pi][j], y);
                u64 u = fma2(t, MONE, S[pi][j]);   // s - t (exact)
                Cn[pi][j] = add2(y, u);            // y - (t - s)
                S[pi][j]  = t;
            }

        __syncthreads();
    }

    float bb[4];
#pragma unroll
    for (int j = 0; j < 4; j++) bb[j] = bias ? bias[n0 + tcol + j] : 0.f;

#pragma unroll
    for (int pi = 0; pi < 4; pi++) {
        float lo[4], hi[4];
#pragma unroll
        for (int j = 0; j < 4; j++) {
            float2 v = unpk2(S[pi][j]);
            float xl = v.x + bb[j];
            float xh = v.y + bb[j];
            if (act == 1)      { xl = fmaxf(xl, 0.f); xh = fmaxf(xh, 0.f); }
            else if (act == 2) { xl = tanhf(xl);      xh = tanhf(xh); }
            lo[j] = xl; hi[j] = xh;
        }
        float* cp0 = C + (size_t)(m0 + trow + 2 * pi)     * N + n0 + tcol;
        float* cp1 = C + (size_t)(m0 + trow + 2 * pi + 1) * N + n0 + tcol;
        *(float4*)cp0 = *(float4*)&lo[0];
        *(float4*)cp1 = *(float4*)&hi[0];
    }
}

// ---------------- epilogue: softmax + top2 + scatter (memory-bound) ---------
// One warp per token; lane l owns experts l and l+32. Reads precomputed
// logits from g_l.
#define EPI_THREADS 256   // 8 warps -> 8 tokens per block

__global__ __launch_bounds__(EPI_THREADS) void epilogue_kernel(
    float* __restrict__ out, int out_size)
{
    const int tid  = threadIdx.x;
    const int lane = tid & 31;
    const int warp = tid >> 5;
    const int b    = blockIdx.x * (EPI_THREADS / 32) + warp;

    const int  OFF_L = BTOK * NEXP;
    const int  OFF_W = 2 * BTOK * NEXP;
    const int  OFF_I = 3 * BTOK * NEXP;
    const bool wl = out_size >= OFF_W;
    const bool ww = out_size >= OFF_I;
    const bool wi = out_size >= OFF_I + 2 * BTOK;

    const size_t base = (size_t)b * NEXP;
    const float l0 = g_l[base + lane];
    const float l1 = g_l[base + lane + 32];

    // softmax over 64
    float m = fmaxf(l0, l1);
#pragma unroll
    for (int off = 16; off; off >>= 1)
        m = fmaxf(m, __shfl_xor_sync(0xffffffffu, m, off));
    const float e0 = expf(l0 - m);
    const float e1 = expf(l1 - m);
    float sden = e0 + e1;
#pragma unroll
    for (int off = 16; off; off >>= 1)
        sden += __shfl_xor_sync(0xffffffffu, sden, off);
    const float w0 = e0 / sden;
    const float w1 = e1 / sden;

    // top-1 (lower index wins ties -> matches jax.lax.top_k)
    float bv; int bi;
    if (w0 >= w1) { bv = w0; bi = lane; } else { bv = w1; bi = lane + 32; }
#pragma unroll
    for (int off = 16; off; off >>= 1) {
        float ov = __shfl_xor_sync(0xffffffffu, bv, off);
        int   oi = __shfl_xor_sync(0xffffffffu, bi, off);
        if (ov > bv || (ov == bv && oi < bi)) { bv = ov; bi = oi; }
    }
    // top-2 (exclude bi; weights >= 0 so -1 acts as -inf)
    float d0 = (lane == bi)      ? -1.f : w0;
    float d1 = (lane + 32 == bi) ? -1.f : w1;
    float bv2; int bi2;
    if (d0 >= d1) { bv2 = d0; bi2 = lane; } else { bv2 = d1; bi2 = lane + 32; }
#pragma unroll
    for (int off = 16; off; off >>= 1) {
        float ov = __shfl_xor_sync(0xffffffffu, bv2, off);
        int   oi = __shfl_xor_sync(0xffffffffu, bi2, off);
        if (ov > bv2 || (ov == bv2 && oi < bi2)) { bv2 = ov; bi2 = oi; }
    }

    const float denom = bv + bv2 + 1e-6f;
    const float r1 = bv / denom;
    const float r2 = bv2 / denom;

    const float cA = (lane == bi)      ? r1 : (lane == bi2)      ? r2 : 0.f;
    const float cB = (lane + 32 == bi) ? r1 : (lane + 32 == bi2) ? r2 : 0.f;
    out[base + lane]      = cA;
    out[base + lane + 32] = cB;
    if (wl) { out[OFF_L + base + lane] = l0; out[OFF_L + base + lane + 32] = l1; }
    if (ww) { out[OFF_W + base + lane] = w0; out[OFF_W + base + lane + 32] = w1; }
    if (wi && lane == 0) {
        out[OFF_I + (size_t)b * 2]     = (float)bi;
        out[OFF_I + (size_t)b * 2 + 1] = (float)bi2;
    }
}

// ---------------- launch ----------------------------------------------------
extern "C" void kernel_launch(void* const* d_in, const int* in_sizes, int n_in,
                              void* d_out, int out_size)
{
    const float* mm    = (const float*)d_in[0];
    const float* qf    = (const float*)d_in[1];
    const float* W_qe1 = (const float*)d_in[2];
    const float* b_qe1 = (const float*)d_in[3];
    const float* W_qe2 = (const float*)d_in[4];
    const float* b_qe2 = (const float*)d_in[5];
    const float* W_fus = (const float*)d_in[6];
    const float* b_fus = (const float*)d_in[7];
    const float* W_g1  = (const float*)d_in[8];
    const float* W_g2  = (const float*)d_in[9];
    float* out = (float*)d_out;

    float *p_q1, *p_q, *p_t, *p_l;
    cudaGetSymbolAddress((void**)&p_q1, g_q1);
    cudaGetSymbolAddress((void**)&p_q,  g_q);
    cudaGetSymbolAddress((void**)&p_t,  g_t);
    cudaGetSymbolAddress((void**)&p_l,  g_l);

    const dim3 blk(256);
    const int mblocks = BTOK / BM;   // 512

    // q1 = relu(qf @ W_qe1^T + b_qe1)
    gemm_bias_act<<<dim3(HID / BN, mblocks), blk>>>(
        qf, nullptr, DIN, DIN, W_qe1, b_qe1, p_q1, HID, 1);
    // q = q1 @ W_qe2^T + b_qe2
    gemm_bias_act<<<dim3(HID / BN, mblocks), blk>>>(
        p_q1, nullptr, HID, HID, W_qe2, b_qe2, p_q, HID, 0);
    // fused = relu([mm | q] @ W_fus^T + b_fus)   (reuses g_q1)
    gemm_bias_act<<<dim3(HID / BN, mblocks), blk>>>(
        mm, p_q, HID, 2 * HID, W_fus, b_fus, p_q1, HID, 1);
    // t = tanh(fused @ W_g1^T)
    gemm_bias_act<<<dim3(FOURE / BN, mblocks), blk>>>(
        p_q1, nullptr, HID, HID, W_g1, nullptr, p_t, FOURE, 2);
    // logits = t @ W_g2^T
    gemm_bias_act<<<dim3(NEXP / BN, mblocks), blk>>>(
        p_t, nullptr, FOURE, FOURE, W_g2, nullptr, p_l, NEXP, 0);

    // softmax + top2 + scatter (memory-bound)
    epilogue_kernel<<<BTOK / (EPI_THREADS / 32), EPI_THREADS>>>(out, out_size);
}

// round 8
// speedup vs baseline: 1.5082x; 1.5082x over previous
#include <cuda_runtime.h>
#include <cstdint>

// Problem constants
#define BTOK  65536
#define HID   512
#define DIN   512
#define NEXP  64
#define FOURE 256

// ---------------- scratch (static __device__, no allocation) ----------------
__device__ float g_q1[(size_t)BTOK * HID];   // qe1 output, reused for fused
__device__ float g_q [(size_t)BTOK * HID];   // qe2 output
__device__ float g_t [(size_t)BTOK * FOURE]; // tanh(fused @ Wg1^T)
__device__ float g_l [(size_t)BTOK * NEXP];  // logits

// ---------------- packed f32x2 helpers (sm_103a) ----------------------------
typedef unsigned long long u64;

__device__ __forceinline__ u64 fma2(u64 a, u64 b, u64 c) {
    u64 d;
    asm("fma.rn.f32x2 %0, %1, %2, %3;" : "=l"(d) : "l"(a), "l"(b), "l"(c));
    return d;
}
__device__ __forceinline__ u64 add2(u64 a, u64 b) {
    u64 d;
    asm("add.rn.f32x2 %0, %1, %2;" : "=l"(d) : "l"(a), "l"(b));
    return d;
}
__device__ __forceinline__ u64 dup2(float x) {
    u64 d;
    asm("mov.b64 %0, {%1, %1};" : "=l"(d) : "f"(x));
    return d;
}
__device__ __forceinline__ float2 unpk2(u64 a) {
    float2 r;
    asm("mov.b64 {%0, %1}, %2;" : "=f"(r.x), "=f"(r.y) : "l"(a));
    return r;
}

// ---------------- chunked-Kahan tiled fp32 GEMM: C = act(A @ W^T) -----------
// ROUND-6 inner loop (empirically best: LDS.64 a-pairs broadcast + LDS.32 b
// + dup2; wide strided LDS.128 regressed via bank conflicts).
// Each BKK=16 k-tile accumulates with plain packed FMA into P (1 op / 2 MACs);
// P is folded into (S, Cn) with a packed Kahan step (Cn = -compensation).
// A is logically [M, K]; columns [0,K0) from A0 (row stride K0), columns
// [K0,K) from A1 (row stride K-K0).  W is [N, K] row-major.
#define BM 128
#define BN 64
#define BKK 16

__global__ __launch_bounds__(256, 2) void gemm_bias_act(
    const float* __restrict__ A0, const float* __restrict__ A1, int K0, int K,
    const float* __restrict__ W, const float* __restrict__ bias,
    float* __restrict__ C, int N, int act)
{
    __shared__ float As[BKK][BM];
    __shared__ float Bs[BKK][BN];

    const int tid  = threadIdx.x;
    const int m0   = blockIdx.y * BM;
    const int n0   = blockIdx.x * BN;
    const int lr   = tid >> 2;          // 0..63
    const int lc   = (tid & 3) << 2;    // 0,4,8,12 (float4 col)
    const int trow = (tid >> 4) << 3;   // 0..120 step 8
    const int tcol = (tid & 15) << 2;   // 0..60 step 4

    const u64 MONE = 0xbf800000bf800000ULL;  // (-1.0f, -1.0f)

    // S[pi][j]: rows (trow+2pi, trow+2pi+1), col tcol+j.  Cn = -compensation.
    u64 S[4][4], Cn[4][4];
#pragma unroll
    for (int pi = 0; pi < 4; pi++)
#pragma unroll
        for (int j = 0; j < 4; j++) { S[pi][j] = 0ull; Cn[pi][j] = 0ull; }

    for (int kt = 0; kt < K; kt += BKK) {
        const int gk = kt + lc;
        float4 av0, av1;
        if (gk < K0) {
            av0 = *(const float4*)(A0 + (size_t)(m0 + lr)      * K0 + gk);
            av1 = *(const float4*)(A0 + (size_t)(m0 + lr + 64) * K0 + gk);
        } else {
            const int K1 = K - K0;
            av0 = *(const float4*)(A1 + (size_t)(m0 + lr)      * K1 + (gk - K0));
            av1 = *(const float4*)(A1 + (size_t)(m0 + lr + 64) * K1 + (gk - K0));
        }
        const float4 bv = *(const float4*)(W + (size_t)(n0 + lr) * K + gk);

        As[lc + 0][lr] = av0.x; As[lc + 1][lr] = av0.y;
        As[lc + 2][lr] = av0.z; As[lc + 3][lr] = av0.w;
        As[lc + 0][lr + 64] = av1.x; As[lc + 1][lr + 64] = av1.y;
        As[lc + 2][lr + 64] = av1.z; As[lc + 3][lr + 64] = av1.w;

        Bs[lc + 0][lr] = bv.x; Bs[lc + 1][lr] = bv.y;
        Bs[lc + 2][lr] = bv.z; Bs[lc + 3][lr] = bv.w;

        __syncthreads();

        // chunk accumulators (plain packed FMA, 16 independent chains)
        u64 P[4][4];
#pragma unroll
        for (int pi = 0; pi < 4; pi++)
#pragma unroll
            for (int j = 0; j < 4; j++) P[pi][j] = 0ull;

#pragma unroll
        for (int k = 0; k < BKK; k++) {
            u64 ap[4];
#pragma unroll
            for (int pi = 0; pi < 4; pi++)
                ap[pi] = *(const u64*)&As[k][trow + 2 * pi];   // LDS.64 row pair
            u64 bd[4];
#pragma unroll
            for (int j = 0; j < 4; j++)
                bd[j] = dup2(Bs[k][tcol + j]);                 // (b, b)
#pragma unroll
            for (int j = 0; j < 4; j++)
#pragma unroll
                for (int pi = 0; pi < 4; pi++)
                    P[pi][j] = fma2(ap[pi], bd[j], P[pi][j]);
        }

        // Kahan fold of chunk sums into (S, Cn)
#pragma unroll
        for (int pi = 0; pi < 4; pi++)
#pragma unroll
            for (int j = 0; j < 4; j++) {
                u64 y = add2(P[pi][j], Cn[pi][j]);
                u64 t = add2(S[pi][j], y);
                u64 u = fma2(t, MONE, S[pi][j]);   // s - t (exact)
                Cn[pi][j] = add2(y, u);            // y - (t - s)
                S[pi][j]  = t;
            }

        __syncthreads();
    }

    float bb[4];
#pragma unroll
    for (int j = 0; j < 4; j++) bb[j] = bias ? bias[n0 + tcol + j] : 0.f;

#pragma unroll
    for (int pi = 0; pi < 4; pi++) {
        float lo[4], hi[4];
#pragma unroll
        for (int j = 0; j < 4; j++) {
            float2 v = unpk2(S[pi][j]);
            float xl = v.x + bb[j];
            float xh = v.y + bb[j];
            if (act == 1)      { xl = fmaxf(xl, 0.f); xh = fmaxf(xh, 0.f); }
            else if (act == 2) { xl = tanhf(xl);      xh = tanhf(xh); }
            lo[j] = xl; hi[j] = xh;
        }
        float* cp0 = C + (size_t)(m0 + trow + 2 * pi)     * N + n0 + tcol;
        float* cp1 = C + (size_t)(m0 + trow + 2 * pi + 1) * N + n0 + tcol;
        *(float4*)cp0 = *(float4*)&lo[0];
        *(float4*)cp1 = *(float4*)&hi[0];
    }
}

// ---------------- epilogue: softmax + top2 + scatter (memory-bound) ---------
// One warp per token; lane l owns experts l and l+32. Reads precomputed
// logits from g_l.
#define EPI_THREADS 256   // 8 warps -> 8 tokens per block

__global__ __launch_bounds__(EPI_THREADS) void epilogue_kernel(
    float* __restrict__ out, int out_size)
{
    const int tid  = threadIdx.x;
    const int lane = tid & 31;
    const int warp = tid >> 5;
    const int b    = blockIdx.x * (EPI_THREADS / 32) + warp;

    const int  OFF_L = BTOK * NEXP;
    const int  OFF_W = 2 * BTOK * NEXP;
    const int  OFF_I = 3 * BTOK * NEXP;
    const bool wl = out_size >= OFF_W;
    const bool ww = out_size >= OFF_I;
    const bool wi = out_size >= OFF_I + 2 * BTOK;

    const size_t base = (size_t)b * NEXP;
    const float l0 = g_l[base + lane];
    const float l1 = g_l[base + lane + 32];

    // softmax over 64
    float m = fmaxf(l0, l1);
#pragma unroll
    for (int off = 16; off; off >>= 1)
        m = fmaxf(m, __shfl_xor_sync(0xffffffffu, m, off));
    const float e0 = expf(l0 - m);
    const float e1 = expf(l1 - m);
    float sden = e0 + e1;
#pragma unroll
    for (int off = 16; off; off >>= 1)
        sden += __shfl_xor_sync(0xffffffffu, sden, off);
    const float w0 = e0 / sden;
    const float w1 = e1 / sden;

    // top-1 (lower index wins ties -> matches jax.lax.top_k)
    float bv; int bi;
    if (w0 >= w1) { bv = w0; bi = lane; } else { bv = w1; bi = lane + 32; }
#pragma unroll
    for (int off = 16; off; off >>= 1) {
        float ov = __shfl_xor_sync(0xffffffffu, bv, off);
        int   oi = __shfl_xor_sync(0xffffffffu, bi, off);
        if (ov > bv || (ov == bv && oi < bi)) { bv = ov; bi = oi; }
    }
    // top-2 (exclude bi; weights >= 0 so -1 acts as -inf)
    float d0 = (lane == bi)      ? -1.f : w0;
    float d1 = (lane + 32 == bi) ? -1.f : w1;
    float bv2; int bi2;
    if (d0 >= d1) { bv2 = d0; bi2 = lane; } else { bv2 = d1; bi2 = lane + 32; }
#pragma unroll
    for (int off = 16; off; off >>= 1) {
        float ov = __shfl_xor_sync(0xffffffffu, bv2, off);
        int   oi = __shfl_xor_sync(0xffffffffu, bi2, off);
        if (ov > bv2 || (ov == bv2 && oi < bi2)) { bv2 = ov; bi2 = oi; }
    }

    const float denom = bv + bv2 + 1e-6f;
    const float r1 = bv / denom;
    const float r2 = bv2 / denom;

    const float cA = (lane == bi)      ? r1 : (lane == bi2)      ? r2 : 0.f;
    const float cB = (lane + 32 == bi) ? r1 : (lane + 32 == bi2) ? r2 : 0.f;
    out[base + lane]      = cA;
    out[base + lane + 32] = cB;
    if (wl) { out[OFF_L + base + lane] = l0; out[OFF_L + base + lane + 32] = l1; }
    if (ww) { out[OFF_W + base + lane] = w0; out[OFF_W + base + lane + 32] = w1; }
    if (wi && lane == 0) {
        out[OFF_I + (size_t)b * 2]     = (float)bi;
        out[OFF_I + (size_t)b * 2 + 1] = (float)bi2;
    }
}

// ---------------- launch ----------------------------------------------------
extern "C" void kernel_launch(void* const* d_in, const int* in_sizes, int n_in,
                              void* d_out, int out_size)
{
    const float* mm    = (const float*)d_in[0];
    const float* qf    = (const float*)d_in[1];
    const float* W_qe1 = (const float*)d_in[2];
    const float* b_qe1 = (const float*)d_in[3];
    const float* W_qe2 = (const float*)d_in[4];
    const float* b_qe2 = (const float*)d_in[5];
    const float* W_fus = (const float*)d_in[6];
    const float* b_fus = (const float*)d_in[7];
    const float* W_g1  = (const float*)d_in[8];
    const float* W_g2  = (const float*)d_in[9];
    float* out = (float*)d_out;

    float *p_q1, *p_q, *p_t, *p_l;
    cudaGetSymbolAddress((void**)&p_q1, g_q1);
    cudaGetSymbolAddress((void**)&p_q,  g_q);
    cudaGetSymbolAddress((void**)&p_t,  g_t);
    cudaGetSymbolAddress((void**)&p_l,  g_l);

    const dim3 blk(256);
    const int mblocks = BTOK / BM;   // 512

    // q1 = relu(qf @ W_qe1^T + b_qe1)
    gemm_bias_act<<<dim3(HID / BN, mblocks), blk>>>(
        qf, nullptr, DIN, DIN, W_qe1, b_qe1, p_q1, HID, 1);
    // q = q1 @ W_qe2^T + b_qe2
    gemm_bias_act<<<dim3(HID / BN, mblocks), blk>>>(
        p_q1, nullptr, HID, HID, W_qe2, b_qe2, p_q, HID, 0);
    // fused = relu([mm | q] @ W_fus^T + b_fus)   (reuses g_q1)
    gemm_bias_act<<<dim3(HID / BN, mblocks), blk>>>(
        mm, p_q, HID, 2 * HID, W_fus, b_fus, p_q1, HID, 1);
    // t = tanh(fused @ W_g1^T)
    gemm_bias_act<<<dim3(FOURE / BN, mblocks), blk>>>(
        p_q1, nullptr, HID, HID, W_g1, nullptr, p_t, FOURE, 2);
    // logits = t @ W_g2^T
    gemm_bias_act<<<dim3(NEXP / BN, mblocks), blk>>>(
        p_t, nullptr, FOURE, FOURE, W_g2, nullptr, p_l, NEXP, 0);

    // softmax + top2 + scatter (memory-bound)
    epilogue_kernel<<<BTOK / (EPI_THREADS / 32), EPI_THREADS>>>(out, out_size);
}